// round 15
// baseline (speedup 1.0000x reference)
#include <cuda_runtime.h>
#include <math.h>
#include <stdint.h>

// Problem constants
#define B_   4
#define LV   2048
#define LE   64
#define LJ   2112     // Lv + Le
#define D_   960
#define H_   15
#define KVH_ 5
#define HD_  64
#define GQA  3        // H / KVH

// Scratch (device globals: no allocation allowed)
__device__ __align__(16) float g_xn  [B_ * LJ * D_];
__device__ __align__(16) float g_q   [B_ * LJ * H_  * HD_];
__device__ __align__(16) float g_k   [B_ * LJ * KVH_* HD_];
__device__ __align__(16) float g_v   [B_ * LJ * KVH_* HD_];
__device__ __align__(16) float g_attn[B_ * LJ * H_  * HD_];

// -------------------------------------------------------------------------
// helpers
// -------------------------------------------------------------------------
__device__ __forceinline__ uint32_t f2tf(float f) {
    uint32_t u;
    asm("cvt.rna.tf32.f32 %0, %1;" : "=r"(u) : "f"(f));
    return u;
}

__device__ __forceinline__ void mma_tf32(float d[4], const uint32_t a[4], const uint32_t b[2]) {
    asm volatile(
        "mma.sync.aligned.m16n8k8.row.col.f32.tf32.tf32.f32 "
        "{%0,%1,%2,%3}, {%4,%5,%6,%7}, {%8,%9}, {%0,%1,%2,%3};"
        : "+f"(d[0]), "+f"(d[1]), "+f"(d[2]), "+f"(d[3])
        : "r"(a[0]), "r"(a[1]), "r"(a[2]), "r"(a[3]), "r"(b[0]), "r"(b[1]));
}

__device__ __forceinline__ void cp16(uint32_t dst_smem, const void* src) {
    asm volatile("cp.async.cg.shared.global [%0], [%1], 16;" :: "r"(dst_smem), "l"(src));
}
#define CP_COMMIT() asm volatile("cp.async.commit_group;")
#define CP_WAIT1()  asm volatile("cp.async.wait_group 1;")
#define CP_WAIT0()  asm volatile("cp.async.wait_group 0;")

// -------------------------------------------------------------------------
// RMSNorm
// -------------------------------------------------------------------------
__global__ void rmsnorm_kernel(const float* __restrict__ h, const float* __restrict__ w,
                               float* __restrict__ out, int Lseg, int offset)
{
    int m = blockIdx.x;
    int b = m / Lseg, r = m % Lseg;
    const float* x = h + (size_t)m * D_;
    float* y = out + ((size_t)(b * LJ + offset + r)) * D_;

    float ss = 0.f;
    for (int i = threadIdx.x; i < D_; i += blockDim.x) { float t = x[i]; ss += t * t; }

    __shared__ float red[32];
    for (int o = 16; o; o >>= 1) ss += __shfl_down_sync(0xffffffffu, ss, o);
    if ((threadIdx.x & 31) == 0) red[threadIdx.x >> 5] = ss;
    __syncthreads();
    if (threadIdx.x < 32) {
        float v2 = (threadIdx.x < (blockDim.x >> 5)) ? red[threadIdx.x] : 0.f;
        for (int o = 16; o; o >>= 1) v2 += __shfl_down_sync(0xffffffffu, v2, o);
        if (threadIdx.x == 0) red[0] = rsqrtf(v2 / (float)D_ + 1e-6f);
    }
    __syncthreads();
    float rs = red[0];
    for (int i = threadIdx.x; i < D_; i += blockDim.x) y[i] = x[i] * rs * w[i];
}

// -------------------------------------------------------------------------
// tf32 tensor-core GEMM, cp.async double-buffered.
// BM=256, BN=64, BK=32; 8 warps (4M x 2N), warp tile 64x32
// (per k8: 16 a-LDS + 8 b-LDS -> 16 MMAs).
// Smem raw fp32 (HMMA tf32 reads top bits). Pads: As 36, Bs 72 (conflict-free).
// -------------------------------------------------------------------------
__global__ __launch_bounds__(256, 2)
void gemm_tc(const float* __restrict__ A, const float* __restrict__ W,
             float* __restrict__ C,
             int Lseg, int offset, int lda, int ldw, int ldc,
             const float* __restrict__ residual, int ldres, int K)
{
    __shared__ float As[2][256 * 36];
    __shared__ float Bs[2][32 * 72];

    int tid = threadIdx.x;
    int lane = tid & 31, wid = tid >> 5;
    int wm = wid >> 1;          // 0..3 -> 64-row slab
    int wn = wid & 1;           // 0..1 -> 32-col slab
    int lr = lane >> 2, lc = lane & 3;
    int row0 = blockIdx.x * 256;
    int col0 = blockIdx.y * 64;

    // Per-thread load coordinates (A: 8 float4/tile, B: 2 float4/tile)
    int ar[8], ac4[8], aoff[8];
    #pragma unroll
    for (int i = 0; i < 8; i++) {
        int li = tid + i * 256;
        ar[i] = li >> 3; ac4[i] = li & 7;
        int gr = row0 + ar[i];
        int arow = (gr / Lseg) * LJ + offset + (gr % Lseg);
        aoff[i] = arow * lda + ac4[i] * 4;
    }
    int br[2], bc4[2], boff[2];
    #pragma unroll
    for (int i = 0; i < 2; i++) {
        int li = tid + i * 256;
        br[i] = li >> 4; bc4[i] = li & 15;
        boff[i] = br[i] * ldw + col0 + bc4[i] * 4;
    }

    uint32_t asb = (uint32_t)__cvta_generic_to_shared(&As[0][0]);
    uint32_t bsb = (uint32_t)__cvta_generic_to_shared(&Bs[0][0]);

    auto load_tile = [&](int k0, int buf) {
        #pragma unroll
        for (int i = 0; i < 8; i++)
            cp16(asb + (buf * 256 * 36 + ar[i] * 36 + ac4[i] * 4) * 4, A + aoff[i] + k0);
        #pragma unroll
        for (int i = 0; i < 2; i++)
            cp16(bsb + (buf * 32 * 72 + br[i] * 72 + bc4[i] * 4) * 4, W + boff[i] + k0 * ldw);
        CP_COMMIT();
    };

    float acc[4][4][4];
    #pragma unroll
    for (int mt = 0; mt < 4; mt++)
        #pragma unroll
        for (int nt = 0; nt < 4; nt++)
            #pragma unroll
            for (int i = 0; i < 4; i++) acc[mt][nt][i] = 0.f;

    int ntiles = K >> 5;
    load_tile(0, 0);

    for (int t = 0; t < ntiles; t++) {
        if (t + 1 < ntiles) { load_tile((t + 1) << 5, (t + 1) & 1); CP_WAIT1(); }
        else CP_WAIT0();
        __syncthreads();

        const float* Ab = As[t & 1];
        const float* Bb = Bs[t & 1];
        #pragma unroll
        for (int k8 = 0; k8 < 4; k8++) {
            uint32_t a[4][4];
            #pragma unroll
            for (int mt = 0; mt < 4; mt++) {
                int r = wm * 64 + mt * 16 + lr;
                int c = k8 * 8 + lc;
                a[mt][0] = __float_as_uint(Ab[r * 36 + c]);
                a[mt][1] = __float_as_uint(Ab[(r + 8) * 36 + c]);
                a[mt][2] = __float_as_uint(Ab[r * 36 + c + 4]);
                a[mt][3] = __float_as_uint(Ab[(r + 8) * 36 + c + 4]);
            }
            #pragma unroll
            for (int nt = 0; nt < 4; nt++) {
                int n = wn * 32 + nt * 8 + lr;
                int kk = k8 * 8 + lc;
                uint32_t bb[2];
                bb[0] = __float_as_uint(Bb[kk * 72 + n]);
                bb[1] = __float_as_uint(Bb[(kk + 4) * 72 + n]);
                #pragma unroll
                for (int mt = 0; mt < 4; mt++)
                    mma_tf32(acc[mt][nt], a[mt], bb);
            }
        }
        __syncthreads();
    }

    #pragma unroll
    for (int mt = 0; mt < 4; mt++) {
        int m0 = row0 + wm * 64 + mt * 16 + lr;
        #pragma unroll
        for (int hh = 0; hh < 2; hh++) {
            int gm = m0 + hh * 8;
            int cm = (gm / Lseg) * LJ + offset + (gm % Lseg);
            #pragma unroll
            for (int nt = 0; nt < 4; nt++) {
                int gc = col0 + wn * 32 + nt * 8 + lc * 2;
                float v0 = acc[mt][nt][hh * 2 + 0];
                float v1 = acc[mt][nt][hh * 2 + 1];
                if (residual) {
                    v0 += residual[(size_t)gm * ldres + gc];
                    v1 += residual[(size_t)gm * ldres + gc + 1];
                }
                float2 o; o.x = v0; o.y = v1;
                *(float2*)(C + (size_t)cm * ldc + gc) = o;
            }
        }
    }
}

// -------------------------------------------------------------------------
// RoPE
// -------------------------------------------------------------------------
__global__ void rope_kernel(const int* __restrict__ pos_v, const int* __restrict__ pos_e)
{
    const int total = B_ * LJ * (H_ + KVH_) * (HD_ / 2);
    int idx = blockIdx.x * blockDim.x + threadIdx.x;
    if (idx >= total) return;
    int dh   = idx & 31;
    int t    = idx >> 5;
    int head = t % (H_ + KVH_);
    int tok  = t / (H_ + KVH_);
    int b = tok / LJ, i = tok % LJ;

    int p = (i < LV) ? pos_v[b * LV + i] : pos_e[b * LE + (i - LV)];
    float ts  = powf(10000.0f, (float)dh * (2.0f / 64.0f));
    float rad = (float)p / ts;
    float sn, cs;
    sincosf(rad, &sn, &cs);

    float* base;
    if (head < H_) base = g_q + (((size_t)(b * LJ + i)) * H_   + head)        * HD_;
    else           base = g_k + (((size_t)(b * LJ + i)) * KVH_ + (head - H_)) * HD_;

    float x1 = base[dh], x2 = base[dh + 32];
    base[dh]      = x1 * cs - x2 * sn;
    base[dh + 32] = x2 * cs + x1 * sn;
}

// -------------------------------------------------------------------------
// Tensor-core flash attention, 128 queries/CTA, 256 threads (8 warps x 16 rows),
// cp.async double-buffered K/V tiles of 32 keys.
// Exp block (q0=2048, only 64 valid rows): loads clamped to row LJ-1, stores guarded.
// -------------------------------------------------------------------------
__global__ __launch_bounds__(256)
void attn_tc()
{
    __shared__ uint32_t Qs[128 * 68];
    __shared__ float    Kt[2][32 * 68];
    __shared__ float    Vs[2][32 * 72];
    __shared__ uint32_t Ps[128 * 36];

    int tid = threadIdx.x;
    int lane = tid & 31, wid = tid >> 5;
    int lr = lane >> 2, lc = lane & 3;
    int q0 = blockIdx.x * 128;
    int bh = blockIdx.y;
    int b = bh / H_, h = bh % H_;
    int kvh = h / GQA;

    // Load Q tile (128x64), clamp row, scale, rna->tf32 : 8 float4/thread
    #pragma unroll
    for (int i = 0; i < 8; i++) {
        int li = tid + i * 256;
        int r = li >> 4, c4 = li & 15;
        int qrow = q0 + r; if (qrow > LJ - 1) qrow = LJ - 1;
        const float* qp = g_q + (((size_t)(b * LJ + qrow)) * H_ + h) * HD_ + c4 * 4;
        float4 v = *(const float4*)qp;
        uint32_t* s = &Qs[r * 68 + c4 * 4];
        s[0] = f2tf(v.x * 0.125f); s[1] = f2tf(v.y * 0.125f);
        s[2] = f2tf(v.z * 0.125f); s[3] = f2tf(v.w * 0.125f);
    }

    bool is_exp = (q0 >= LV);
    int ntiles = (is_exp ? LJ : LV) >> 5;

    // K/V load coords: 2 cp.async each per thread
    int kr[2], kc4[2];
    #pragma unroll
    for (int i = 0; i < 2; i++) { int li = tid + i * 256; kr[i] = li >> 4; kc4[i] = li & 15; }
    uint32_t ktb = (uint32_t)__cvta_generic_to_shared(&Kt[0][0]);
    uint32_t vsb = (uint32_t)__cvta_generic_to_shared(&Vs[0][0]);

    auto load_kv = [&](int k0, int buf) {
        #pragma unroll
        for (int i = 0; i < 2; i++) {
            size_t off = (((size_t)(b * LJ + k0 + kr[i])) * KVH_ + kvh) * HD_ + kc4[i] * 4;
            cp16(ktb + (buf * 32 * 68 + kr[i] * 68 + kc4[i] * 4) * 4, g_k + off);
            cp16(vsb + (buf * 32 * 72 + kr[i] * 72 + kc4[i] * 4) * 4, g_v + off);
        }
        CP_COMMIT();
    };

    float O[8][4];
    #pragma unroll
    for (int nt = 0; nt < 8; nt++)
        #pragma unroll
        for (int i = 0; i < 4; i++) O[nt][i] = 0.f;
    float m0r = -1e30f, m1r = -1e30f;
    float l0r = 0.f,    l1r = 0.f;

    load_kv(0, 0);

    for (int t = 0; t < ntiles; t++) {
        int k0 = t << 5;
        if (t + 1 < ntiles) { load_kv((t + 1) << 5, (t + 1) & 1); CP_WAIT1(); }
        else CP_WAIT0();
        __syncthreads();

        const float* Kb = Kt[t & 1];
        const float* Vb = Vs[t & 1];

        // S = Q * K^T
        float S[4][4];
        #pragma unroll
        for (int nt = 0; nt < 4; nt++)
            #pragma unroll
            for (int i = 0; i < 4; i++) S[nt][i] = 0.f;

        #pragma unroll
        for (int k8 = 0; k8 < 8; k8++) {
            uint32_t a[4];
            int r = wid * 16 + lr;
            int c = k8 * 8 + lc;
            a[0] = Qs[r * 68 + c];
            a[1] = Qs[(r + 8) * 68 + c];
            a[2] = Qs[r * 68 + c + 4];
            a[3] = Qs[(r + 8) * 68 + c + 4];
            #pragma unroll
            for (int nt = 0; nt < 4; nt++) {
                uint32_t bb[2];
                int key = nt * 8 + lr;
                bb[0] = __float_as_uint(Kb[key * 68 + k8 * 8 + lc]);
                bb[1] = __float_as_uint(Kb[key * 68 + k8 * 8 + lc + 4]);
                mma_tf32(S[nt], a, bb);
            }
        }

        // Causal mask (exp block, tiles crossing/after LV)
        if (is_exp && k0 + 32 > LV) {
            int qi0 = q0 + wid * 16 + lr;
            #pragma unroll
            for (int nt = 0; nt < 4; nt++) {
                int jg = k0 + nt * 8 + lc * 2;
                if (jg     > qi0)     S[nt][0] = -1e30f;
                if (jg + 1 > qi0)     S[nt][1] = -1e30f;
                if (jg     > qi0 + 8) S[nt][2] = -1e30f;
                if (jg + 1 > qi0 + 8) S[nt][3] = -1e30f;
            }
        }

        // Online softmax
        float mt0 = -1e30f, mt1 = -1e30f;
        #pragma unroll
        for (int nt = 0; nt < 4; nt++) {
            mt0 = fmaxf(mt0, fmaxf(S[nt][0], S[nt][1]));
            mt1 = fmaxf(mt1, fmaxf(S[nt][2], S[nt][3]));
        }
        mt0 = fmaxf(mt0, __shfl_xor_sync(0xffffffffu, mt0, 1));
        mt0 = fmaxf(mt0, __shfl_xor_sync(0xffffffffu, mt0, 2));
        mt1 = fmaxf(mt1, __shfl_xor_sync(0xffffffffu, mt1, 1));
        mt1 = fmaxf(mt1, __shfl_xor_sync(0xffffffffu, mt1, 2));

        float mn0 = fmaxf(m0r, mt0), mn1 = fmaxf(m1r, mt1);
        float c0 = __expf(m0r - mn0), c1 = __expf(m1r - mn1);
        m0r = mn0; m1r = mn1;

        #pragma unroll
        for (int nt = 0; nt < 8; nt++) {
            O[nt][0] *= c0; O[nt][1] *= c0;
            O[nt][2] *= c1; O[nt][3] *= c1;
        }

        float ps0 = 0.f, ps1 = 0.f;
        #pragma unroll
        for (int nt = 0; nt < 4; nt++) {
            S[nt][0] = __expf(S[nt][0] - mn0);
            S[nt][1] = __expf(S[nt][1] - mn0);
            S[nt][2] = __expf(S[nt][2] - mn1);
            S[nt][3] = __expf(S[nt][3] - mn1);
            ps0 += S[nt][0] + S[nt][1];
            ps1 += S[nt][2] + S[nt][3];
        }
        ps0 += __shfl_xor_sync(0xffffffffu, ps0, 1);
        ps0 += __shfl_xor_sync(0xffffffffu, ps0, 2);
        ps1 += __shfl_xor_sync(0xffffffffu, ps1, 1);
        ps1 += __shfl_xor_sync(0xffffffffu, ps1, 2);
        l0r = l0r * c0 + ps0;
        l1r = l1r * c1 + ps1;

        // P -> smem (tf32), warp-private 16-row region
        {
            int r = wid * 16 + lr;
            #pragma unroll
            for (int nt = 0; nt < 4; nt++) {
                int kc = nt * 8 + lc * 2;
                Ps[r * 36 + kc]           = f2tf(S[nt][0]);
                Ps[r * 36 + kc + 1]       = f2tf(S[nt][1]);
                Ps[(r + 8) * 36 + kc]     = f2tf(S[nt][2]);
                Ps[(r + 8) * 36 + kc + 1] = f2tf(S[nt][3]);
            }
        }
        __syncwarp();

        // O += P * V
        #pragma unroll
        for (int k8 = 0; k8 < 4; k8++) {
            uint32_t a[4];
            int r = wid * 16 + lr;
            int c = k8 * 8 + lc;
            a[0] = Ps[r * 36 + c];
            a[1] = Ps[(r + 8) * 36 + c];
            a[2] = Ps[r * 36 + c + 4];
            a[3] = Ps[(r + 8) * 36 + c + 4];
            #pragma unroll
            for (int nt = 0; nt < 8; nt++) {
                uint32_t bb[2];
                bb[0] = __float_as_uint(Vb[(k8 * 8 + lc) * 72 + nt * 8 + lr]);
                bb[1] = __float_as_uint(Vb[(k8 * 8 + lc + 4) * 72 + nt * 8 + lr]);
                mma_tf32(O[nt], a, bb);
            }
        }
        __syncthreads();   // buffer reuse fence
    }

    // Epilogue (guard invalid rows in exp block)
    float inv0 = 1.f / l0r, inv1 = 1.f / l1r;
    int qi0 = q0 + wid * 16 + lr;
    if (qi0 < LJ) {
        float* op0 = g_attn + ((size_t)(b * LJ + qi0)) * (H_ * HD_) + h * HD_;
        #pragma unroll
        for (int nt = 0; nt < 8; nt++) {
            int col = nt * 8 + lc * 2;
            float2 o0; o0.x = O[nt][0] * inv0; o0.y = O[nt][1] * inv0;
            *(float2*)(op0 + col) = o0;
        }
    }
    if (qi0 + 8 < LJ) {
        float* op1 = g_attn + ((size_t)(b * LJ + qi0 + 8)) * (H_ * HD_) + h * HD_;
        #pragma unroll
        for (int nt = 0; nt < 8; nt++) {
            int col = nt * 8 + lc * 2;
            float2 o1; o1.x = O[nt][2] * inv1; o1.y = O[nt][3] * inv1;
            *(float2*)(op1 + col) = o1;
        }
    }
}

// -------------------------------------------------------------------------
// Launch
// -------------------------------------------------------------------------
extern "C" void kernel_launch(void* const* d_in, const int* in_sizes, int n_in,
                              void* d_out, int out_size)
{
    const float* h_v  = (const float*)d_in[0];
    const float* h_e  = (const float*)d_in[1];
    const float* ln_v = (const float*)d_in[2];
    const float* wq_v = (const float*)d_in[3];
    const float* wk_v = (const float*)d_in[4];
    const float* wv_v = (const float*)d_in[5];
    const float* wo_v = (const float*)d_in[6];
    const float* ln_e = (const float*)d_in[7];
    const float* wq_e = (const float*)d_in[8];
    const float* wk_e = (const float*)d_in[9];
    const float* wv_e = (const float*)d_in[10];
    const float* wo_e = (const float*)d_in[11];
    const int*  pos_v = (const int*)d_in[12];
    const int*  pos_e = (const int*)d_in[13];
    float* out = (float*)d_out;

    float *xn, *q, *k, *v, *attn;
    cudaGetSymbolAddress((void**)&xn,   g_xn);
    cudaGetSymbolAddress((void**)&q,    g_q);
    cudaGetSymbolAddress((void**)&k,    g_k);
    cudaGetSymbolAddress((void**)&v,    g_v);
    cudaGetSymbolAddress((void**)&attn, g_attn);

    // 1) RMSNorm into joint-layout xn
    rmsnorm_kernel<<<B_ * LV, 256>>>(h_v, ln_v, xn, LV, 0);
    rmsnorm_kernel<<<B_ * LE, 256>>>(h_e, ln_e, xn, LE, LV);

    // 2) QKV GEMMs (tf32, BM=256)
    dim3 gqv(32, 15), gkv(32, 5), gqe(1, 15), gke(1, 5);
    gemm_tc<<<gqv, 256>>>(xn, wq_v, q, LV, 0,  D_, 960, 960, nullptr, 0, D_);
    gemm_tc<<<gkv, 256>>>(xn, wk_v, k, LV, 0,  D_, 320, 320, nullptr, 0, D_);
    gemm_tc<<<gkv, 256>>>(xn, wv_v, v, LV, 0,  D_, 320, 320, nullptr, 0, D_);
    gemm_tc<<<gqe, 256>>>(xn, wq_e, q, LE, LV, D_, 960, 960, nullptr, 0, D_);
    gemm_tc<<<gke, 256>>>(xn, wk_e, k, LE, LV, D_, 320, 320, nullptr, 0, D_);
    gemm_tc<<<gke, 256>>>(xn, wv_e, v, LE, LV, D_, 320, 320, nullptr, 0, D_);

    // 3) RoPE in-place on q, k
    {
        const int total = B_ * LJ * (H_ + KVH_) * (HD_ / 2);
        rope_kernel<<<(total + 255) / 256, 256>>>(pos_v, pos_e);
    }

    // 4) Attention (128 queries/CTA): 16 VLM blocks + 1 exp block
    {
        dim3 grid(17, B_ * H_);
        attn_tc<<<grid, 256>>>();
    }

    // 5) Output projection + residual into d_out
    gemm_tc<<<gqv, 256>>>(attn, wo_v, out, LV, 0,  960, 960, 960, h_v, 960, 960);
    gemm_tc<<<gqe, 256>>>(attn, wo_e, out, LE, LV, 960, 960, 960, h_e, 960, 960);
}